// round 6
// baseline (speedup 1.0000x reference)
#include <cuda_runtime.h>
#include <math.h>

// ---------------- problem constants ----------------
#define B_  4
#define L_  2048
#define D_  1024
#define H_  16
#define HD_ 64
#define M_  (B_ * L_)          // 8192 rows

// ---------------- scratch (device globals; no allocs allowed) ----------------
__device__ float g_q[(size_t)M_ * D_];
__device__ float g_k[(size_t)M_ * D_];
__device__ float g_v[(size_t)M_ * D_];
__device__ float g_o[(size_t)M_ * D_];

// ======================================================================
// GEMM (NT): C[m][n] = sum_k A[m][k] * W[n][k]
// M=8192, N=1024, K=1024. 128x128 block, 8x8 per thread, BK=8.
// ======================================================================
#define GBM 128
#define GBN 128
#define GBK 8

__global__ void __launch_bounds__(256, 2)
gemm_nt_kernel(const float* __restrict__ A, const float* __restrict__ W,
               float* __restrict__ C) {
    __shared__ float As[GBK][GBM + 4];
    __shared__ float Bs[GBK][GBN + 4];

    const int tid = threadIdx.x;
    const int bm  = blockIdx.y * GBM;
    const int bn  = blockIdx.x * GBN;
    const int tx  = tid & 15;         // 0..15  -> 8 cols each
    const int ty  = tid >> 4;         // 0..15  -> 8 rows each

    // load mapping: 128 rows x 8 k = 1024 floats = 256 float4
    const int lr = tid >> 1;          // 0..127
    const int lc = (tid & 1) * 4;     // 0 or 4

    const float* Ap = A + (size_t)(bm + lr) * D_ + lc;
    const float* Wp = W + (size_t)(bn + lr) * D_ + lc;

    float acc[8][8];
#pragma unroll
    for (int i = 0; i < 8; i++)
#pragma unroll
        for (int j = 0; j < 8; j++) acc[i][j] = 0.f;

    float4 afrag = *(const float4*)Ap;
    float4 wfrag = *(const float4*)Wp;

    for (int k0 = 0; k0 < D_; k0 += GBK) {
        // store current tiles to smem (transposed)
        As[lc + 0][lr] = afrag.x; As[lc + 1][lr] = afrag.y;
        As[lc + 2][lr] = afrag.z; As[lc + 3][lr] = afrag.w;
        Bs[lc + 0][lr] = wfrag.x; Bs[lc + 1][lr] = wfrag.y;
        Bs[lc + 2][lr] = wfrag.z; Bs[lc + 3][lr] = wfrag.w;
        __syncthreads();

        // prefetch next tiles (latency hidden by compute below)
        if (k0 + GBK < D_) {
            afrag = *(const float4*)(Ap + k0 + GBK);
            wfrag = *(const float4*)(Wp + k0 + GBK);
        }

#pragma unroll
        for (int kk = 0; kk < GBK; kk++) {
            float ar[8], br[8];
            *(float4*)(ar)     = *(float4*)(&As[kk][ty * 8]);
            *(float4*)(ar + 4) = *(float4*)(&As[kk][ty * 8 + 4]);
            *(float4*)(br)     = *(float4*)(&Bs[kk][tx * 8]);
            *(float4*)(br + 4) = *(float4*)(&Bs[kk][tx * 8 + 4]);
#pragma unroll
            for (int i = 0; i < 8; i++)
#pragma unroll
                for (int j = 0; j < 8; j++)
                    acc[i][j] += ar[i] * br[j];
        }
        __syncthreads();
    }

#pragma unroll
    for (int i = 0; i < 8; i++) {
        float* crow = C + (size_t)(bm + ty * 8 + i) * D_ + bn + tx * 8;
        *(float4*)(crow)     = make_float4(acc[i][0], acc[i][1], acc[i][2], acc[i][3]);
        *(float4*)(crow + 4) = make_float4(acc[i][4], acc[i][5], acc[i][6], acc[i][7]);
    }
}

// ======================================================================
// RoPE (in-place on g_q, g_k); folds score scale 1/sqrt(hd)=0.125 into q.
// Pair (f, f+32) within each 64-dim head, theta = pos * 10000^(-f/32).
// ======================================================================
__global__ void __launch_bounds__(256)
rope_kernel(float* __restrict__ q, float* __restrict__ k) {
    const int idx = blockIdx.x * blockDim.x + threadIdx.x;  // over M_ * 512 pairs
    if (idx >= M_ * (D_ / 2)) return;
    const int m = idx >> 9;           // row 0..8191
    const int p = idx & 511;          // pair index within row
    const int h = p >> 5;             // head
    const int f = p & 31;             // freq index
    const int pos = m & (L_ - 1);     // position within sequence

    // inv_freq in double for fidelity, then fp32 multiply like the reference
    const float inv_freq = (float)exp(-(double)f * (log(10000.0) / 32.0));
    const float theta = (float)pos * inv_freq;
    float s, c;
    sincosf(theta, &s, &c);

    const size_t j0 = (size_t)m * D_ + h * HD_ + f;
    const size_t j1 = j0 + 32;

    float q0 = q[j0], q1 = q[j1];
    q[j0] = (q0 * c - q1 * s) * 0.125f;
    q[j1] = (q1 * c + q0 * s) * 0.125f;

    float k0 = k[j0], k1 = k[j1];
    k[j0] = k0 * c - k1 * s;
    k[j1] = k1 * c + k0 * s;
}

// ======================================================================
// Flash attention, fp32. One block = one (b,h) + one 64-row q tile.
// 8 warps; warp w owns q-rows w*8..w*8+7. Lane owns cols {lane, lane+32}.
// smem tiles 64x64 padded to stride 68 (conflict-free LDS128 column reads:
// 68 floats = 272B, 272 mod 128 = 16 -> perfect 8-lane permutation).
// ======================================================================
#define TS 64
#define SROW 68
#define ATTN_SMEM (4 * TS * SROW * (int)sizeof(float))   // 69632 B

__global__ void __launch_bounds__(256, 2)
attn_kernel(const float* __restrict__ gq, const float* __restrict__ gk,
            const float* __restrict__ gv, float* __restrict__ go) {
    extern __shared__ float sm[];
    float* Qs = sm;                    // TS * SROW
    float* Ks = Qs + TS * SROW;
    float* Vs = Ks + TS * SROW;
    float* Ps = Vs + TS * SROW;

    const int qt  = blockIdx.x;        // 0..31
    const int bh  = blockIdx.y;        // 0..63
    const int b   = bh >> 4;
    const int h   = bh & 15;
    const int tid = threadIdx.x;
    const int warp = tid >> 5, lane = tid & 31;

    const float* qbase = gq + (size_t)b * L_ * D_ + h * HD_;
    const float* kbase = gk + (size_t)b * L_ * D_ + h * HD_;
    const float* vbase = gv + (size_t)b * L_ * D_ + h * HD_;

    // load Q tile (64 rows x 64 cols = 1024 float4)
    for (int i = tid; i < TS * 16; i += 256) {
        const int r = i >> 4, c4 = (i & 15) * 4;
        *(float4*)(&Qs[r * SROW + c4]) =
            *(const float4*)(qbase + (size_t)(qt * TS + r) * D_ + c4);
    }

    const int r0 = warp * 8;
    const int c0 = lane, c1 = lane + 32;   // score cols / value dims owned by lane
    float m_i[8], l_i[8], o0[8], o1[8];
#pragma unroll
    for (int r = 0; r < 8; r++) { m_i[r] = -1e30f; l_i[r] = 0.f; o0[r] = 0.f; o1[r] = 0.f; }

    __syncthreads();

    for (int kt = 0; kt < L_ / TS; kt++) {
        // cooperative K,V tile load
        for (int i = tid; i < TS * 16; i += 256) {
            const int r = i >> 4, c4 = (i & 15) * 4;
            const size_t off = (size_t)(kt * TS + r) * D_ + c4;
            *(float4*)(&Ks[r * SROW + c4]) = *(const float4*)(kbase + off);
            *(float4*)(&Vs[r * SROW + c4]) = *(const float4*)(vbase + off);
        }
        __syncthreads();

        // S = Q K^T for this warp's 8 rows, lane's 2 cols
        float s0[8], s1[8];
#pragma unroll
        for (int r = 0; r < 8; r++) { s0[r] = 0.f; s1[r] = 0.f; }
#pragma unroll
        for (int dd = 0; dd < 16; dd++) {
            const float4 k0 = *(float4*)(&Ks[c0 * SROW + dd * 4]);
            const float4 k1 = *(float4*)(&Ks[c1 * SROW + dd * 4]);
#pragma unroll
            for (int r = 0; r < 8; r++) {
                const float4 qv = *(float4*)(&Qs[(r0 + r) * SROW + dd * 4]);
                s0[r] += qv.x * k0.x + qv.y * k0.y + qv.z * k0.z + qv.w * k0.w;
                s1[r] += qv.x * k1.x + qv.y * k1.y + qv.z * k1.z + qv.w * k1.w;
            }
        }

        // online softmax update (scale already folded into q)
#pragma unroll
        for (int r = 0; r < 8; r++) {
            float mx = fmaxf(s0[r], s1[r]);
#pragma unroll
            for (int off = 16; off; off >>= 1)
                mx = fmaxf(mx, __shfl_xor_sync(0xffffffffu, mx, off));
            const float mnew = fmaxf(m_i[r], mx);
            const float alpha = __expf(m_i[r] - mnew);
            const float p0 = __expf(s0[r] - mnew);
            const float p1 = __expf(s1[r] - mnew);
            float sum = p0 + p1;
#pragma unroll
            for (int off = 16; off; off >>= 1)
                sum += __shfl_xor_sync(0xffffffffu, sum, off);
            l_i[r] = l_i[r] * alpha + sum;
            m_i[r] = mnew;
            o0[r] *= alpha; o1[r] *= alpha;
            Ps[(r0 + r) * SROW + c0] = p0;
            Ps[(r0 + r) * SROW + c1] = p1;
        }
        __syncwarp();   // Ps rows are warp-private; only warp-level ordering needed

        // O += P @ V  (lane's output dims c0,c1)
#pragma unroll
        for (int cc = 0; cc < 16; cc++) {
            const float va0 = Vs[(cc * 4 + 0) * SROW + c0];
            const float va1 = Vs[(cc * 4 + 1) * SROW + c0];
            const float va2 = Vs[(cc * 4 + 2) * SROW + c0];
            const float va3 = Vs[(cc * 4 + 3) * SROW + c0];
            const float vb0 = Vs[(cc * 4 + 0) * SROW + c1];
            const float vb1 = Vs[(cc * 4 + 1) * SROW + c1];
            const float vb2 = Vs[(cc * 4 + 2) * SROW + c1];
            const float vb3 = Vs[(cc * 4 + 3) * SROW + c1];
#pragma unroll
            for (int r = 0; r < 8; r++) {
                const float4 p = *(float4*)(&Ps[(r0 + r) * SROW + cc * 4]);
                o0[r] += p.x * va0 + p.y * va1 + p.z * va2 + p.w * va3;
                o1[r] += p.x * vb0 + p.y * vb1 + p.z * vb2 + p.w * vb3;
            }
        }
        __syncthreads();   // protect Ks/Vs before next tile's load
    }

    // epilogue: normalize and store
    float* obase = go + (size_t)b * L_ * D_ + h * HD_;
#pragma unroll
    for (int r = 0; r < 8; r++) {
        const float inv = 1.f / l_i[r];
        const size_t row = (size_t)(qt * TS + r0 + r) * D_;
        obase[row + c0] = o0[r] * inv;
        obase[row + c1] = o1[r] * inv;
    }
}

// ======================================================================
// launcher
// ======================================================================
extern "C" void kernel_launch(void* const* d_in, const int* in_sizes, int n_in,
                              void* d_out, int out_size) {
    const float* x  = (const float*)d_in[0];
    const float* Wq = (const float*)d_in[1];
    const float* Wk = (const float*)d_in[2];
    const float* Wv = (const float*)d_in[3];
    const float* Wo = (const float*)d_in[4];
    float* out = (float*)d_out;

    float *q, *k, *v, *o;
    cudaGetSymbolAddress((void**)&q, g_q);
    cudaGetSymbolAddress((void**)&k, g_k);
    cudaGetSymbolAddress((void**)&v, g_v);
    cudaGetSymbolAddress((void**)&o, g_o);

    cudaFuncSetAttribute(attn_kernel, cudaFuncAttributeMaxDynamicSharedMemorySize,
                         ATTN_SMEM);

    const dim3 ggrid(D_ / GBN, M_ / GBM);   // (8, 64)
    gemm_nt_kernel<<<ggrid, 256>>>(x, Wq, q);
    gemm_nt_kernel<<<ggrid, 256>>>(x, Wk, k);
    gemm_nt_kernel<<<ggrid, 256>>>(x, Wv, v);

    const int pairs = M_ * (D_ / 2);
    rope_kernel<<<(pairs + 255) / 256, 256>>>(q, k);

    attn_kernel<<<dim3(L_ / TS, B_ * H_), 256, ATTN_SMEM>>>(q, k, v, o);

    gemm_nt_kernel<<<ggrid, 256>>>(o, Wo, out);
}

// round 12
// speedup vs baseline: 2.7842x; 2.7842x over previous
#include <cuda_runtime.h>
#include <cuda_bf16.h>
#include <math.h>
#include <stdint.h>

// ---------------- problem constants ----------------
#define B_  4
#define L_  2048
#define D_  1024
#define H_  16
#define HD_ 64
#define M_  (B_ * L_)          // 8192 rows

// ---------------- scratch (device globals; no allocs allowed) ----------------
__device__ float g_q[(size_t)M_ * D_];
__device__ float g_k[(size_t)M_ * D_];
__device__ float g_v[(size_t)M_ * D_];
__device__ float g_o[(size_t)M_ * D_];
__device__ float g_rcos[L_ * 32];
__device__ float g_rsin[L_ * 32];

// ---------------- mma.sync helpers (base ISA, compiles for compute_103) ----
__device__ __forceinline__ void mma16816(float* c, const uint32_t* a,
                                         const uint32_t* b) {
    asm volatile(
        "mma.sync.aligned.m16n8k16.row.col.f32.bf16.bf16.f32 "
        "{%0,%1,%2,%3}, {%4,%5,%6,%7}, {%8,%9}, {%0,%1,%2,%3};"
        : "+f"(c[0]), "+f"(c[1]), "+f"(c[2]), "+f"(c[3])
        : "r"(a[0]), "r"(a[1]), "r"(a[2]), "r"(a[3]), "r"(b[0]), "r"(b[1]));
}

__device__ __forceinline__ uint32_t pack_hi2(float x, float y) {
    __nv_bfloat162 h = __float22bfloat162_rn(make_float2(x, y));
    return *(uint32_t*)&h;
}
__device__ __forceinline__ uint32_t pack_lo2(float x, float y, uint32_t hi) {
    __nv_bfloat162 h = *(__nv_bfloat162*)&hi;
    float2 r = __bfloat1622float2(h);
    __nv_bfloat162 l = __float22bfloat162_rn(make_float2(x - r.x, y - r.y));
    return *(uint32_t*)&l;
}

// ======================================================================
// bf16-split GEMM on mma.sync (NT): C[m][n] = sum_k A[m][k] * W[n][k]
// C ~= Ah*Wh + Ah*Wl + Al*Wh  (lo*lo dropped).
// Block 128x128, 8 warps (4x2) of 32x64 warp tiles, BK=32, double buffer.
// ======================================================================
#define GS_STRIDE 40                          // bf16 per smem row (padded)
#define GS_TILE   (128 * GS_STRIDE)           // 5120 bf16 = 10240 B
#define GS_BUF_B  (4 * GS_TILE * 2)           // Ah,Al,Wh,Wl = 40960 B
#define GSMEM     (2 * GS_BUF_B)              // 81920 B

__device__ __forceinline__ uint32_t lds32g(const char* base, int r, int k) {
    return *(const uint32_t*)(base + (r * GS_STRIDE + k) * 2);
}

__device__ __forceinline__ void store_hilo(char* hi, char* lo, int r, int c4,
                                           float4 v, int stride) {
    uint32_t h01 = pack_hi2(v.x, v.y);
    uint32_t h23 = pack_hi2(v.z, v.w);
    uint32_t l01 = pack_lo2(v.x, v.y, h01);
    uint32_t l23 = pack_lo2(v.z, v.w, h23);
    const int off = (r * stride + c4) * 2;
    *(uint2*)(hi + off) = make_uint2(h01, h23);
    *(uint2*)(lo + off) = make_uint2(l01, l23);
}

__global__ void __launch_bounds__(256, 2)
gemm_tc_kernel(const float* __restrict__ A, const float* __restrict__ W,
               float* __restrict__ C) {
    extern __shared__ char gsm[];
    const int tid = threadIdx.x;
    const int wid = tid >> 5, lane = tid & 31;
    const int bm = blockIdx.y * 128;
    const int bn = blockIdx.x * 128;
    const int wm = (wid >> 1) * 32;
    const int wn = (wid & 1) * 64;
    const int qid = lane >> 2;
    const int tq  = lane & 3;

    float acc[2][8][4];
#pragma unroll
    for (int mi = 0; mi < 2; mi++)
#pragma unroll
        for (int ni = 0; ni < 8; ni++)
#pragma unroll
            for (int j = 0; j < 4; j++) acc[mi][ni][j] = 0.f;

    for (int ch = 0; ch < D_ / 32; ch++) {
        char* buf = gsm + (ch & 1) * GS_BUF_B;
        char* sAh = buf;
        char* sAl = buf + GS_TILE * 2;
        char* sWh = buf + 2 * GS_TILE * 2;
        char* sWl = buf + 3 * GS_TILE * 2;
        const int k0 = ch * 32;

#pragma unroll
        for (int i = 0; i < 4; i++) {
            const int idx = tid + i * 256;
            const int r = idx >> 3;
            const int c4 = (idx & 7) * 4;
            float4 av = *(const float4*)(A + (size_t)(bm + r) * D_ + k0 + c4);
            store_hilo(sAh, sAl, r, c4, av, GS_STRIDE);
            float4 wv = *(const float4*)(W + (size_t)(bn + r) * D_ + k0 + c4);
            store_hilo(sWh, sWl, r, c4, wv, GS_STRIDE);
        }
        __syncthreads();

#pragma unroll
        for (int ks = 0; ks < 2; ks++) {
            const int kb = ks * 16 + tq * 2;
            uint32_t ah[2][4], wh[8][2];
#pragma unroll
            for (int mi = 0; mi < 2; mi++) {
                const int r = wm + mi * 16 + qid;
                ah[mi][0] = lds32g(sAh, r,     kb);
                ah[mi][1] = lds32g(sAh, r + 8, kb);
                ah[mi][2] = lds32g(sAh, r,     kb + 8);
                ah[mi][3] = lds32g(sAh, r + 8, kb + 8);
            }
#pragma unroll
            for (int ni = 0; ni < 8; ni++) {
                const int r = wn + ni * 8 + qid;
                wh[ni][0] = lds32g(sWh, r, kb);
                wh[ni][1] = lds32g(sWh, r, kb + 8);
            }
#pragma unroll
            for (int mi = 0; mi < 2; mi++)
#pragma unroll
                for (int ni = 0; ni < 8; ni++)
                    mma16816(acc[mi][ni], ah[mi], wh[ni]);      // hi*hi

            uint32_t wl[8][2];
#pragma unroll
            for (int ni = 0; ni < 8; ni++) {
                const int r = wn + ni * 8 + qid;
                wl[ni][0] = lds32g(sWl, r, kb);
                wl[ni][1] = lds32g(sWl, r, kb + 8);
            }
#pragma unroll
            for (int mi = 0; mi < 2; mi++)
#pragma unroll
                for (int ni = 0; ni < 8; ni++)
                    mma16816(acc[mi][ni], ah[mi], wl[ni]);      // hi*lo

            uint32_t al[2][4];
#pragma unroll
            for (int mi = 0; mi < 2; mi++) {
                const int r = wm + mi * 16 + qid;
                al[mi][0] = lds32g(sAl, r,     kb);
                al[mi][1] = lds32g(sAl, r + 8, kb);
                al[mi][2] = lds32g(sAl, r,     kb + 8);
                al[mi][3] = lds32g(sAl, r + 8, kb + 8);
            }
#pragma unroll
            for (int mi = 0; mi < 2; mi++)
#pragma unroll
                for (int ni = 0; ni < 8; ni++)
                    mma16816(acc[mi][ni], al[mi], wh[ni]);      // lo*hi
        }
    }

#pragma unroll
    for (int mi = 0; mi < 2; mi++) {
        const int row = bm + wm + mi * 16 + qid;
#pragma unroll
        for (int ni = 0; ni < 8; ni++) {
            const int col = bn + wn + ni * 8 + tq * 2;
            *(float2*)(C + (size_t)row * D_ + col) =
                make_float2(acc[mi][ni][0], acc[mi][ni][1]);
            *(float2*)(C + (size_t)(row + 8) * D_ + col) =
                make_float2(acc[mi][ni][2], acc[mi][ni][3]);
        }
    }
}

// ======================================================================
// RoPE table + apply (table kills the per-element double exp).
// ======================================================================
__global__ void __launch_bounds__(256)
rope_table_kernel() {
    const int idx = blockIdx.x * 256 + threadIdx.x;
    if (idx >= L_ * 32) return;
    const int pos = idx >> 5, f = idx & 31;
    const float inv_freq = (float)exp(-(double)f * 0.28782313662425572);  // ln(1e4)/32
    const float theta = (float)pos * inv_freq;
    float s, c;
    sincosf(theta, &s, &c);
    g_rcos[idx] = c;
    g_rsin[idx] = s;
}

__global__ void __launch_bounds__(256)
rope_kernel(float* __restrict__ q, float* __restrict__ k) {
    const int idx = blockIdx.x * blockDim.x + threadIdx.x;
    if (idx >= M_ * (D_ / 2)) return;
    const int m = idx >> 9;
    const int p = idx & 511;
    const int h = p >> 5;
    const int f = p & 31;
    const int pos = m & (L_ - 1);

    const int t = (pos << 5) | f;
    const float c = g_rcos[t];
    const float s = g_rsin[t];

    const size_t j0 = (size_t)m * D_ + h * HD_ + f;
    const size_t j1 = j0 + 32;

    float q0 = q[j0], q1 = q[j1];
    q[j0] = (q0 * c - q1 * s) * 0.125f;
    q[j1] = (q1 * c + q0 * s) * 0.125f;

    float k0 = k[j0], k1 = k[j1];
    k[j0] = k0 * c - k1 * s;
    k[j1] = k1 * c + k0 * s;
}

// ======================================================================
// Flash attention on mma.sync, bf16-split both matmuls.
// Block = (b,h) x 128 q-rows, 8 warps x 16 q-rows. KV tiles of 64,
// double-buffered smem (K as [kv][d], V transposed [d][kv], hi+lo each),
// single __syncthreads per tile. Q fragments register-resident.
// ======================================================================
#define AST   72                          // bf16 stride (conflict-free frags)
#define ATILE (64 * AST * 2)              // 9216 B per sub-tile
#define ABUF  (4 * ATILE)                 // Kh,Kl,Vth,Vtl = 36864 B
#define ASMEM (2 * ABUF)                  // 73728 B

__device__ __forceinline__ uint32_t lds32a(const char* base, int r, int k) {
    return *(const uint32_t*)(base + (r * AST + k) * 2);
}

__global__ void __launch_bounds__(256, 1)
attn_kernel(const float* __restrict__ gq, const float* __restrict__ gk,
            const float* __restrict__ gv, float* __restrict__ go) {
    extern __shared__ char asmem[];

    const int qt  = blockIdx.x;            // 0..15 (q tile of 128)
    const int bh  = blockIdx.y;            // 0..63
    const int b   = bh >> 4;
    const int h   = bh & 15;
    const int tid = threadIdx.x;
    const int warp = tid >> 5, lane = tid & 31;
    const int qid = lane >> 2, tq = lane & 3;
    const int wq = warp * 16;              // warp's q-row base within tile

    const float* qbase = gq + (size_t)b * L_ * D_ + h * HD_;
    const float* kbase = gk + (size_t)b * L_ * D_ + h * HD_;
    const float* vbase = gv + (size_t)b * L_ * D_ + h * HD_;

    // ---- Q fragments (register-resident for whole kv loop) ----
    const float* qr0 = qbase + (size_t)(qt * 128 + wq + qid) * D_;
    const float* qr1 = qr0 + 8 * D_;
    uint32_t qh[4][4], ql[4][4];
#pragma unroll
    for (int t = 0; t < 4; t++) {
        float2 f0 = *(const float2*)(qr0 + t * 16 + 2 * tq);
        float2 f1 = *(const float2*)(qr1 + t * 16 + 2 * tq);
        float2 f2 = *(const float2*)(qr0 + t * 16 + 2 * tq + 8);
        float2 f3 = *(const float2*)(qr1 + t * 16 + 2 * tq + 8);
        qh[t][0] = pack_hi2(f0.x, f0.y); ql[t][0] = pack_lo2(f0.x, f0.y, qh[t][0]);
        qh[t][1] = pack_hi2(f1.x, f1.y); ql[t][1] = pack_lo2(f1.x, f1.y, qh[t][1]);
        qh[t][2] = pack_hi2(f2.x, f2.y); ql[t][2] = pack_lo2(f2.x, f2.y, qh[t][2]);
        qh[t][3] = pack_hi2(f3.x, f3.y); ql[t][3] = pack_lo2(f3.x, f3.y, qh[t][3]);
    }

    float oc[8][4];
#pragma unroll
    for (int j = 0; j < 8; j++)
#pragma unroll
        for (int c = 0; c < 4; c++) oc[j][c] = 0.f;
    float m0 = -1e30f, m1 = -1e30f, l0 = 0.f, l1 = 0.f;

    // gmem->reg prefetch of tile 0
    float4 kf[4], vf[4];
#pragma unroll
    for (int i = 0; i < 4; i++) {
        const int idx = tid + i * 256;
        const int r = idx >> 4, c4 = (idx & 15) * 4;
        kf[i] = *(const float4*)(kbase + (size_t)r * D_ + c4);
        vf[i] = *(const float4*)(vbase + (size_t)r * D_ + c4);
    }

    for (int ch = 0; ch < L_ / 64; ch++) {
        char* buf = asmem + (ch & 1) * ABUF;
        char* sKh = buf;
        char* sKl = buf + ATILE;
        char* sVh = buf + 2 * ATILE;
        char* sVl = buf + 3 * ATILE;

        // ---- store prefetched tile: K [kv][d], V transposed [d][kv] ----
#pragma unroll
        for (int i = 0; i < 4; i++) {
            const int idx = tid + i * 256;
            const int r = idx >> 4, c4 = (idx & 15) * 4;
            store_hilo(sKh, sKl, r, c4, kf[i], AST);
            // V transpose: element (kv=r, d=c4+e) -> sV[d][kv]
            const float vv[4] = {vf[i].x, vf[i].y, vf[i].z, vf[i].w};
#pragma unroll
            for (int e = 0; e < 4; e++) {
                __nv_bfloat16 hb = __float2bfloat16(vv[e]);
                __nv_bfloat16 lb = __float2bfloat16(vv[e] - __bfloat162float(hb));
                const int off = ((c4 + e) * AST + r) * 2;
                *(__nv_bfloat16*)(sVh + off) = hb;
                *(__nv_bfloat16*)(sVl + off) = lb;
            }
        }
        __syncthreads();

        // prefetch next tile while computing this one
        if (ch + 1 < L_ / 64) {
            const size_t base = (size_t)(ch + 1) * 64 * D_;
#pragma unroll
            for (int i = 0; i < 4; i++) {
                const int idx = tid + i * 256;
                const int r = idx >> 4, c4 = (idx & 15) * 4;
                kf[i] = *(const float4*)(kbase + base + (size_t)r * D_ + c4);
                vf[i] = *(const float4*)(vbase + base + (size_t)r * D_ + c4);
            }
        }

        // ---- S = Q K^T (3-term split) ----
        float sc[8][4];
#pragma unroll
        for (int j = 0; j < 8; j++)
#pragma unroll
            for (int c = 0; c < 4; c++) sc[j][c] = 0.f;

#pragma unroll
        for (int t = 0; t < 4; t++) {
            const int kb = t * 16 + 2 * tq;
#pragma unroll
            for (int j = 0; j < 8; j++) {
                const int r = j * 8 + qid;
                uint32_t bh2[2], bl2[2];
                bh2[0] = lds32a(sKh, r, kb);     bh2[1] = lds32a(sKh, r, kb + 8);
                bl2[0] = lds32a(sKl, r, kb);     bl2[1] = lds32a(sKl, r, kb + 8);
                mma16816(sc[j], qh[t], bh2);     // hi*hi
                mma16816(sc[j], qh[t], bl2);     // hi*lo
                mma16816(sc[j], ql[t], bh2);     // lo*hi
            }
        }

        // ---- online softmax (register fragments, FA2 layout) ----
        float mx0 = -1e30f, mx1 = -1e30f;
#pragma unroll
        for (int j = 0; j < 8; j++) {
            mx0 = fmaxf(mx0, fmaxf(sc[j][0], sc[j][1]));
            mx1 = fmaxf(mx1, fmaxf(sc[j][2], sc[j][3]));
        }
        mx0 = fmaxf(mx0, __shfl_xor_sync(0xffffffffu, mx0, 1));
        mx0 = fmaxf(mx0, __shfl_xor_sync(0xffffffffu, mx0, 2));
        mx1 = fmaxf(mx1, __shfl_xor_sync(0xffffffffu, mx1, 1));
        mx1 = fmaxf(mx1, __shfl_xor_sync(0xffffffffu, mx1, 2));

        const float mn0 = fmaxf(m0, mx0), mn1 = fmaxf(m1, mx1);
        const float al0 = __expf(m0 - mn0), al1 = __expf(m1 - mn1);
        float sum0 = 0.f, sum1 = 0.f;
#pragma unroll
        for (int j = 0; j < 8; j++) {
            sc[j][0] = __expf(sc[j][0] - mn0);
            sc[j][1] = __expf(sc[j][1] - mn0);
            sc[j][2] = __expf(sc[j][2] - mn1);
            sc[j][3] = __expf(sc[j][3] - mn1);
            sum0 += sc[j][0] + sc[j][1];
            sum1 += sc[j][2] + sc[j][3];
        }
        sum0 += __shfl_xor_sync(0xffffffffu, sum0, 1);
        sum0 += __shfl_xor_sync(0xffffffffu, sum0, 2);
        sum1 += __shfl_xor_sync(0xffffffffu, sum1, 1);
        sum1 += __shfl_xor_sync(0xffffffffu, sum1, 2);
        l0 = l0 * al0 + sum0;  m0 = mn0;
        l1 = l1 * al1 + sum1;  m1 = mn1;
#pragma unroll
        for (int j = 0; j < 8; j++) {
            oc[j][0] *= al0; oc[j][1] *= al0;
            oc[j][2] *= al1; oc[j][3] *= al1;
        }

        // ---- O += P V (3-term split); P frags by register repack ----
#pragma unroll
        for (int t = 0; t < 4; t++) {
            const int j0 = 2 * t, j1 = 2 * t + 1;
            uint32_t ph[4], pl[4];
            ph[0] = pack_hi2(sc[j0][0], sc[j0][1]); pl[0] = pack_lo2(sc[j0][0], sc[j0][1], ph[0]);
            ph[1] = pack_hi2(sc[j0][2], sc[j0][3]); pl[1] = pack_lo2(sc[j0][2], sc[j0][3], ph[1]);
            ph[2] = pack_hi2(sc[j1][0], sc[j1][1]); pl[2] = pack_lo2(sc[j1][0], sc[j1][1], ph[2]);
            ph[3] = pack_hi2(sc[j1][2], sc[j1][3]); pl[3] = pack_lo2(sc[j1][2], sc[j1][3], ph[3]);

            const int kb = t * 16 + 2 * tq;
#pragma unroll
            for (int j = 0; j < 8; j++) {
                const int r = j * 8 + qid;               // d-row of V^T
                uint32_t vh2[2], vl2[2];
                vh2[0] = lds32a(sVh, r, kb);     vh2[1] = lds32a(sVh, r, kb + 8);
                vl2[0] = lds32a(sVl, r, kb);     vl2[1] = lds32a(sVl, r, kb + 8);
                mma16816(oc[j], ph, vh2);        // hi*hi
                mma16816(oc[j], ph, vl2);        // hi*lo
                mma16816(oc[j], pl, vh2);        // lo*hi
            }
        }
        __syncthreads();
    }

    // ---- epilogue ----
    const float inv0 = 1.f / l0, inv1 = 1.f / l1;
    float* or0 = go + (size_t)(b * L_ + qt * 128 + wq + qid) * D_ + h * HD_;
    float* or1 = or0 + 8 * D_;
#pragma unroll
    for (int j = 0; j < 8; j++) {
        const int col = j * 8 + 2 * tq;
        *(float2*)(or0 + col) = make_float2(oc[j][0] * inv0, oc[j][1] * inv0);
        *(float2*)(or1 + col) = make_float2(oc[j][2] * inv1, oc[j][3] * inv1);
    }
}

// ======================================================================
// launcher
// ======================================================================
extern "C" void kernel_launch(void* const* d_in, const int* in_sizes, int n_in,
                              void* d_out, int out_size) {
    const float* x  = (const float*)d_in[0];
    const float* Wq = (const float*)d_in[1];
    const float* Wk = (const float*)d_in[2];
    const float* Wv = (const float*)d_in[3];
    const float* Wo = (const float*)d_in[4];
    float* out = (float*)d_out;

    float *q, *k, *v, *o;
    cudaGetSymbolAddress((void**)&q, g_q);
    cudaGetSymbolAddress((void**)&k, g_k);
    cudaGetSymbolAddress((void**)&v, g_v);
    cudaGetSymbolAddress((void**)&o, g_o);

    cudaFuncSetAttribute(gemm_tc_kernel, cudaFuncAttributeMaxDynamicSharedMemorySize,
                         GSMEM);
    cudaFuncSetAttribute(attn_kernel, cudaFuncAttributeMaxDynamicSharedMemorySize,
                         ASMEM);

    rope_table_kernel<<<(L_ * 32 + 255) / 256, 256>>>();

    const dim3 ggrid(D_ / 128, M_ / 128);   // (8, 64)
    gemm_tc_kernel<<<ggrid, 256, GSMEM>>>(x, Wq, q);
    gemm_tc_kernel<<<ggrid, 256, GSMEM>>>(x, Wk, k);
    gemm_tc_kernel<<<ggrid, 256, GSMEM>>>(x, Wv, v);

    const int pairs = M_ * (D_ / 2);
    rope_kernel<<<(pairs + 255) / 256, 256>>>(q, k);

    attn_kernel<<<dim3(L_ / 128, B_ * H_), 256, ASMEM>>>(q, k, v, o);

    gemm_tc_kernel<<<ggrid, 256, GSMEM>>>(o, Wo, out);
}

// round 13
// speedup vs baseline: 3.6065x; 1.2953x over previous
#include <cuda_runtime.h>
#include <cuda_bf16.h>
#include <math.h>
#include <stdint.h>

// ---------------- problem constants ----------------
#define B_  4
#define L_  2048
#define D_  1024
#define H_  16
#define HD_ 64
#define M_  (B_ * L_)          // 8192 rows

// ---------------- scratch (device globals; no allocs allowed) ----------------
__device__ float g_q[(size_t)M_ * D_];
__device__ float g_k[(size_t)M_ * D_];
__device__ float g_v[(size_t)M_ * D_];
__device__ float g_o[(size_t)M_ * D_];
__device__ float g_rcos[L_ * 32];
__device__ float g_rsin[L_ * 32];

// ---------------- base-ISA mma/ldmatrix helpers ----------------
__device__ __forceinline__ void mma16816(float* c, const uint32_t* a,
                                         const uint32_t* b) {
    asm volatile(
        "mma.sync.aligned.m16n8k16.row.col.f32.bf16.bf16.f32 "
        "{%0,%1,%2,%3}, {%4,%5,%6,%7}, {%8,%9}, {%0,%1,%2,%3};"
        : "+f"(c[0]), "+f"(c[1]), "+f"(c[2]), "+f"(c[3])
        : "r"(a[0]), "r"(a[1]), "r"(a[2]), "r"(a[3]), "r"(b[0]), "r"(b[1]));
}

__device__ __forceinline__ void ldsm_x4(uint32_t* r, uint32_t addr) {
    asm volatile(
        "ldmatrix.sync.aligned.m8n8.x4.shared.b16 {%0,%1,%2,%3}, [%4];"
        : "=r"(r[0]), "=r"(r[1]), "=r"(r[2]), "=r"(r[3]) : "r"(addr));
}

__device__ __forceinline__ void ldsm_x4_t(uint32_t* r, uint32_t addr) {
    asm volatile(
        "ldmatrix.sync.aligned.m8n8.x4.trans.shared.b16 {%0,%1,%2,%3}, [%4];"
        : "=r"(r[0]), "=r"(r[1]), "=r"(r[2]), "=r"(r[3]) : "r"(addr));
}

__device__ __forceinline__ uint32_t s2u(const void* p) {
    return (uint32_t)__cvta_generic_to_shared(p);
}

__device__ __forceinline__ uint32_t pack_hi2(float x, float y) {
    __nv_bfloat162 h = __float22bfloat162_rn(make_float2(x, y));
    return *(uint32_t*)&h;
}
__device__ __forceinline__ uint32_t pack_lo2(float x, float y, uint32_t hi) {
    __nv_bfloat162 h = *(__nv_bfloat162*)&hi;
    float2 r = __bfloat1622float2(h);
    __nv_bfloat162 l = __float22bfloat162_rn(make_float2(x - r.x, y - r.y));
    return *(uint32_t*)&l;
}

__device__ __forceinline__ void store_hilo(char* hi, char* lo, int r, int c4,
                                           float4 v, int stride) {
    uint32_t h01 = pack_hi2(v.x, v.y);
    uint32_t h23 = pack_hi2(v.z, v.w);
    uint32_t l01 = pack_lo2(v.x, v.y, h01);
    uint32_t l23 = pack_lo2(v.z, v.w, h23);
    const int off = (r * stride + c4) * 2;
    *(uint2*)(hi + off) = make_uint2(h01, h23);
    *(uint2*)(lo + off) = make_uint2(l01, l23);
}

// ======================================================================
// bf16-split GEMM on mma.sync (NT): C[m][n] = sum_k A[m][k] * W[n][k]
// C ~= Ah*Wh + Ah*Wl + Al*Wh.  Block 128x128, 8 warps (4x2), BK=32,
// double buffer, ldmatrix fragment loads. grid.z selects W/C (QKV fusion);
// mode=1 applies RoPE (+0.125 fold for z==0) in the epilogue for z<2.
// ======================================================================
#define GS_STRIDE 40                          // bf16 per smem row (padded)
#define GS_TILE   (128 * GS_STRIDE)           // 5120 bf16 = 10240 B
#define GS_BUF_B  (4 * GS_TILE * 2)           // Ah,Al,Wh,Wl = 40960 B
#define GSMEM     (2 * GS_BUF_B)              // 81920 B

__global__ void __launch_bounds__(256, 2)
gemm_tc_kernel(const float* __restrict__ A,
               const float* __restrict__ W0, const float* __restrict__ W1,
               const float* __restrict__ W2,
               float* __restrict__ C0, float* __restrict__ C1,
               float* __restrict__ C2, int mode) {
    extern __shared__ char gsm[];
    const int z = blockIdx.z;
    const float* W = (z == 0) ? W0 : (z == 1) ? W1 : W2;
    float* C       = (z == 0) ? C0 : (z == 1) ? C1 : C2;

    const int tid = threadIdx.x;
    const int wid = tid >> 5, lane = tid & 31;
    const int bm = blockIdx.y * 128;
    const int bn = blockIdx.x * 128;
    const int wm = (wid >> 1) * 32;
    const int wn = (wid & 1) * 64;
    const int qid = lane >> 2;
    const int tq  = lane & 3;

    // ldmatrix lane address components (element units)
    const int rowa = (lane & 7) + (((lane >> 3) & 1) << 3);   // A x4 row
    const int cola = (lane >> 4) << 3;                        // A x4 col
    const int roww = (lane & 7) + ((lane >> 4) << 3);         // W x4 row
    const int colw = ((lane >> 3) & 1) << 3;                  // W x4 col

    float acc[2][8][4];
#pragma unroll
    for (int mi = 0; mi < 2; mi++)
#pragma unroll
        for (int ni = 0; ni < 8; ni++)
#pragma unroll
            for (int j = 0; j < 4; j++) acc[mi][ni][j] = 0.f;

    for (int ch = 0; ch < D_ / 32; ch++) {
        char* buf = gsm + (ch & 1) * GS_BUF_B;
        char* sAh = buf;
        char* sAl = buf + GS_TILE * 2;
        char* sWh = buf + 2 * GS_TILE * 2;
        char* sWl = buf + 3 * GS_TILE * 2;
        const int k0 = ch * 32;

#pragma unroll
        for (int i = 0; i < 4; i++) {
            const int idx = tid + i * 256;
            const int r = idx >> 3;
            const int c4 = (idx & 7) * 4;
            float4 av = *(const float4*)(A + (size_t)(bm + r) * D_ + k0 + c4);
            store_hilo(sAh, sAl, r, c4, av, GS_STRIDE);
            float4 wv = *(const float4*)(W + (size_t)(bn + r) * D_ + k0 + c4);
            store_hilo(sWh, sWl, r, c4, wv, GS_STRIDE);
        }
        __syncthreads();

        const uint32_t uAh = s2u(sAh), uAl = s2u(sAl);
        const uint32_t uWh = s2u(sWh), uWl = s2u(sWl);

#pragma unroll
        for (int ks = 0; ks < 2; ks++) {
            const int kb = ks * 16;
            uint32_t ah[2][4], al[2][4];
#pragma unroll
            for (int mi = 0; mi < 2; mi++) {
                const uint32_t aoff =
                    (uint32_t)(((wm + mi * 16 + rowa) * GS_STRIDE + kb + cola) * 2);
                ldsm_x4(ah[mi], uAh + aoff);
                ldsm_x4(al[mi], uAl + aoff);
            }
#pragma unroll
            for (int nip = 0; nip < 4; nip++) {
                const uint32_t woff =
                    (uint32_t)(((wn + nip * 16 + roww) * GS_STRIDE + kb + colw) * 2);
                uint32_t wh4[4], wl4[4];
                ldsm_x4(wh4, uWh + woff);
                ldsm_x4(wl4, uWl + woff);
#pragma unroll
                for (int mi = 0; mi < 2; mi++) {
                    mma16816(acc[mi][2 * nip],     ah[mi], wh4);       // hi*hi
                    mma16816(acc[mi][2 * nip + 1], ah[mi], wh4 + 2);
                    mma16816(acc[mi][2 * nip],     ah[mi], wl4);       // hi*lo
                    mma16816(acc[mi][2 * nip + 1], ah[mi], wl4 + 2);
                    mma16816(acc[mi][2 * nip],     al[mi], wh4);       // lo*hi
                    mma16816(acc[mi][2 * nip + 1], al[mi], wh4 + 2);
                }
            }
        }
    }

    // ---- fused RoPE epilogue (q/k only): pair (f, f+32) = (ni, ni+4) ----
    if (mode && z < 2) {
        const float qs = (z == 0) ? 0.125f : 1.0f;
#pragma unroll
        for (int mi = 0; mi < 2; mi++) {
            const int r0 = bm + wm + mi * 16 + qid;
            const int pos0 = r0 & (L_ - 1);
            const int pos1 = (r0 + 8) & (L_ - 1);
#pragma unroll
            for (int ni = 0; ni < 4; ni++) {
#pragma unroll
                for (int e = 0; e < 2; e++) {
                    const int f = ni * 8 + tq * 2 + e;
                    const float c0v = g_rcos[pos0 * 32 + f];
                    const float s0v = g_rsin[pos0 * 32 + f];
                    const float c1v = g_rcos[pos1 * 32 + f];
                    const float s1v = g_rsin[pos1 * 32 + f];
                    float x0 = acc[mi][ni][e],     y0 = acc[mi][ni + 4][e];
                    float x1 = acc[mi][ni][e + 2], y1 = acc[mi][ni + 4][e + 2];
                    acc[mi][ni][e]         = (x0 * c0v - y0 * s0v) * qs;
                    acc[mi][ni + 4][e]     = (y0 * c0v + x0 * s0v) * qs;
                    acc[mi][ni][e + 2]     = (x1 * c1v - y1 * s1v) * qs;
                    acc[mi][ni + 4][e + 2] = (y1 * c1v + x1 * s1v) * qs;
                }
            }
        }
    }

#pragma unroll
    for (int mi = 0; mi < 2; mi++) {
        const int row = bm + wm + mi * 16 + qid;
#pragma unroll
        for (int ni = 0; ni < 8; ni++) {
            const int col = bn + wn + ni * 8 + tq * 2;
            *(float2*)(C + (size_t)row * D_ + col) =
                make_float2(acc[mi][ni][0], acc[mi][ni][1]);
            *(float2*)(C + (size_t)(row + 8) * D_ + col) =
                make_float2(acc[mi][ni][2], acc[mi][ni][3]);
        }
    }
}

// ======================================================================
// RoPE table: the expensive double exp runs once per (pos, f) entry.
// ======================================================================
__global__ void __launch_bounds__(256)
rope_table_kernel() {
    const int idx = blockIdx.x * 256 + threadIdx.x;
    if (idx >= L_ * 32) return;
    const int pos = idx >> 5, f = idx & 31;
    const float inv_freq = (float)exp(-(double)f * 0.28782313662425572);  // ln(1e4)/32
    const float theta = (float)pos * inv_freq;
    float s, c;
    sincosf(theta, &s, &c);
    g_rcos[idx] = c;
    g_rsin[idx] = s;
}

// ======================================================================
// Flash attention on mma.sync, bf16-split both matmuls, ldmatrix frags.
// Block = (b,h) x 128 q-rows, 8 warps x 16 q-rows. KV tiles of 64.
// K and V both stored [kv][d] hi/lo; PV B-frags via ldmatrix.trans.
// ======================================================================
#define AST   72                          // bf16 stride (conflict-free LDSM)
#define ATILE (64 * AST * 2)              // 9216 B per sub-tile
#define ABUF  (4 * ATILE)                 // Kh,Kl,Vh,Vl = 36864 B
#define ASMEM (2 * ABUF)                  // 73728 B

__global__ void __launch_bounds__(256, 1)
attn_kernel(const float* __restrict__ gq, const float* __restrict__ gk,
            const float* __restrict__ gv, float* __restrict__ go) {
    extern __shared__ char asmem[];

    const int qt  = blockIdx.x;            // q tile of 128
    const int bh  = blockIdx.y;
    const int b   = bh >> 4;
    const int h   = bh & 15;
    const int tid = threadIdx.x;
    const int warp = tid >> 5, lane = tid & 31;
    const int qid = lane >> 2, tq = lane & 3;
    const int wq = warp * 16;

    // ldmatrix lane address components
    const int rowk = (lane & 7) + ((lane >> 4) << 3);         // K x4 (non-trans B)
    const int colk = ((lane >> 3) & 1) << 3;
    const int rowv = (lane & 7) + (((lane >> 3) & 1) << 3);   // V x4 trans
    const int colv = (lane >> 4) << 3;

    const float* qbase = gq + (size_t)b * L_ * D_ + h * HD_;
    const float* kbase = gk + (size_t)b * L_ * D_ + h * HD_;
    const float* vbase = gv + (size_t)b * L_ * D_ + h * HD_;

    // ---- Q fragments (register-resident for whole kv loop) ----
    const float* qr0 = qbase + (size_t)(qt * 128 + wq + qid) * D_;
    const float* qr1 = qr0 + 8 * D_;
    uint32_t qh[4][4], ql[4][4];
#pragma unroll
    for (int t = 0; t < 4; t++) {
        float2 f0 = *(const float2*)(qr0 + t * 16 + 2 * tq);
        float2 f1 = *(const float2*)(qr1 + t * 16 + 2 * tq);
        float2 f2 = *(const float2*)(qr0 + t * 16 + 2 * tq + 8);
        float2 f3 = *(const float2*)(qr1 + t * 16 + 2 * tq + 8);
        qh[t][0] = pack_hi2(f0.x, f0.y); ql[t][0] = pack_lo2(f0.x, f0.y, qh[t][0]);
        qh[t][1] = pack_hi2(f1.x, f1.y); ql[t][1] = pack_lo2(f1.x, f1.y, qh[t][1]);
        qh[t][2] = pack_hi2(f2.x, f2.y); ql[t][2] = pack_lo2(f2.x, f2.y, qh[t][2]);
        qh[t][3] = pack_hi2(f3.x, f3.y); ql[t][3] = pack_lo2(f3.x, f3.y, qh[t][3]);
    }

    float oc[8][4];
#pragma unroll
    for (int j = 0; j < 8; j++)
#pragma unroll
        for (int c = 0; c < 4; c++) oc[j][c] = 0.f;
    float m0 = -1e30f, m1 = -1e30f, l0 = 0.f, l1 = 0.f;

    // gmem->reg prefetch of tile 0
    float4 kf[4], vf[4];
#pragma unroll
    for (int i = 0; i < 4; i++) {
        const int idx = tid + i * 256;
        const int r = idx >> 4, c4 = (idx & 15) * 4;
        kf[i] = *(const float4*)(kbase + (size_t)r * D_ + c4);
        vf[i] = *(const float4*)(vbase + (size_t)r * D_ + c4);
    }

    for (int ch = 0; ch < L_ / 64; ch++) {
        char* buf = asmem + (ch & 1) * ABUF;
        char* sKh = buf;
        char* sKl = buf + ATILE;
        char* sVh = buf + 2 * ATILE;
        char* sVl = buf + 3 * ATILE;

        // ---- store prefetched tile (both [kv][d], vectorized) ----
#pragma unroll
        for (int i = 0; i < 4; i++) {
            const int idx = tid + i * 256;
            const int r = idx >> 4, c4 = (idx & 15) * 4;
            store_hilo(sKh, sKl, r, c4, kf[i], AST);
            store_hilo(sVh, sVl, r, c4, vf[i], AST);
        }
        __syncthreads();

        // prefetch next tile while computing this one
        if (ch + 1 < L_ / 64) {
            const size_t base = (size_t)(ch + 1) * 64 * D_;
#pragma unroll
            for (int i = 0; i < 4; i++) {
                const int idx = tid + i * 256;
                const int r = idx >> 4, c4 = (idx & 15) * 4;
                kf[i] = *(const float4*)(kbase + base + (size_t)r * D_ + c4);
                vf[i] = *(const float4*)(vbase + base + (size_t)r * D_ + c4);
            }
        }

        const uint32_t uKh = s2u(sKh), uKl = s2u(sKl);
        const uint32_t uVh = s2u(sVh), uVl = s2u(sVl);

        // ---- S = Q K^T (3-term split) ----
        float sc[8][4];
#pragma unroll
        for (int j = 0; j < 8; j++)
#pragma unroll
            for (int c = 0; c < 4; c++) sc[j][c] = 0.f;

#pragma unroll
        for (int t = 0; t < 4; t++) {
#pragma unroll
            for (int jp = 0; jp < 4; jp++) {
                const uint32_t koff =
                    (uint32_t)(((jp * 16 + rowk) * AST + t * 16 + colk) * 2);
                uint32_t bh4[4], bl4[4];
                ldsm_x4(bh4, uKh + koff);
                ldsm_x4(bl4, uKl + koff);
                mma16816(sc[2 * jp],     qh[t], bh4);       // hi*hi
                mma16816(sc[2 * jp + 1], qh[t], bh4 + 2);
                mma16816(sc[2 * jp],     qh[t], bl4);       // hi*lo
                mma16816(sc[2 * jp + 1], qh[t], bl4 + 2);
                mma16816(sc[2 * jp],     ql[t], bh4);       // lo*hi
                mma16816(sc[2 * jp + 1], ql[t], bh4 + 2);
            }
        }

        // ---- online softmax (register fragments) ----
        float mx0 = -1e30f, mx1 = -1e30f;
#pragma unroll
        for (int j = 0; j < 8; j++) {
            mx0 = fmaxf(mx0, fmaxf(sc[j][0], sc[j][1]));
            mx1 = fmaxf(mx1, fmaxf(sc[j][2], sc[j][3]));
        }
        mx0 = fmaxf(mx0, __shfl_xor_sync(0xffffffffu, mx0, 1));
        mx0 = fmaxf(mx0, __shfl_xor_sync(0xffffffffu, mx0, 2));
        mx1 = fmaxf(mx1, __shfl_xor_sync(0xffffffffu, mx1, 1));
        mx1 = fmaxf(mx1, __shfl_xor_sync(0xffffffffu, mx1, 2));

        const float mn0 = fmaxf(m0, mx0), mn1 = fmaxf(m1, mx1);
        const float al0 = __expf(m0 - mn0), al1 = __expf(m1 - mn1);
        float sum0 = 0.f, sum1 = 0.f;
#pragma unroll
        for (int j = 0; j < 8; j++) {
            sc[j][0] = __expf(sc[j][0] - mn0);
            sc[j][1] = __expf(sc[j][1] - mn0);
            sc[j][2] = __expf(sc[j][2] - mn1);
            sc[j][3] = __expf(sc[j][3] - mn1);
            sum0 += sc[j][0] + sc[j][1];
            sum1 += sc[j][2] + sc[j][3];
        }
        sum0 += __shfl_xor_sync(0xffffffffu, sum0, 1);
        sum0 += __shfl_xor_sync(0xffffffffu, sum0, 2);
        sum1 += __shfl_xor_sync(0xffffffffu, sum1, 1);
        sum1 += __shfl_xor_sync(0xffffffffu, sum1, 2);
        l0 = l0 * al0 + sum0;  m0 = mn0;
        l1 = l1 * al1 + sum1;  m1 = mn1;
#pragma unroll
        for (int j = 0; j < 8; j++) {
            oc[j][0] *= al0; oc[j][1] *= al0;
            oc[j][2] *= al1; oc[j][3] *= al1;
        }

        // ---- O += P V (3-term split); V frags via ldmatrix.trans ----
#pragma unroll
        for (int t = 0; t < 4; t++) {
            const int j0 = 2 * t, j1 = 2 * t + 1;
            uint32_t ph[4], pl[4];
            ph[0] = pack_hi2(sc[j0][0], sc[j0][1]); pl[0] = pack_lo2(sc[j0][0], sc[j0][1], ph[0]);
            ph[1] = pack_hi2(sc[j0][2], sc[j0][3]); pl[1] = pack_lo2(sc[j0][2], sc[j0][3], ph[1]);
            ph[2] = pack_hi2(sc[j1][0], sc[j1][1]); pl[2] = pack_lo2(sc[j1][0], sc[j1][1], ph[2]);
            ph[3] = pack_hi2(sc[j1][2], sc[j1][3]); pl[3] = pack_lo2(sc[j1][2], sc[j1][3], ph[3]);

#pragma unroll
            for (int jp = 0; jp < 4; jp++) {
                const uint32_t voff =
                    (uint32_t)(((t * 16 + rowv) * AST + jp * 16 + colv) * 2);
                uint32_t vh4[4], vl4[4];
                ldsm_x4_t(vh4, uVh + voff);
                ldsm_x4_t(vl4, uVl + voff);
                mma16816(oc[2 * jp],     ph, vh4);          // hi*hi
                mma16816(oc[2 * jp + 1], ph, vh4 + 2);
                mma16816(oc[2 * jp],     ph, vl4);          // hi*lo
                mma16816(oc[2 * jp + 1], ph, vl4 + 2);
                mma16816(oc[2 * jp],     pl, vh4);          // lo*hi
                mma16816(oc[2 * jp + 1], pl, vh4 + 2);
            }
        }
        __syncthreads();
    }

    // ---- epilogue ----
    const float inv0 = 1.f / l0, inv1 = 1.f / l1;
    float* or0 = go + (size_t)(b * L_ + qt * 128 + wq + qid) * D_ + h * HD_;
    float* or1 = or0 + 8 * D_;
#pragma unroll
    for (int j = 0; j < 8; j++) {
        const int col = j * 8 + 2 * tq;
        *(float2*)(or0 + col) = make_float2(oc[j][0] * inv0, oc[j][1] * inv0);
        *(float2*)(or1 + col) = make_float2(oc[j][2] * inv1, oc[j][3] * inv1);
    }
}

// ======================================================================
// launcher
// ======================================================================
extern "C" void kernel_launch(void* const* d_in, const int* in_sizes, int n_in,
                              void* d_out, int out_size) {
    const float* x  = (const float*)d_in[0];
    const float* Wq = (const float*)d_in[1];
    const float* Wk = (const float*)d_in[2];
    const float* Wv = (const float*)d_in[3];
    const float* Wo = (const float*)d_in[4];
    float* out = (float*)d_out;

    float *q, *k, *v, *o;
    cudaGetSymbolAddress((void**)&q, g_q);
    cudaGetSymbolAddress((void**)&k, g_k);
    cudaGetSymbolAddress((void**)&v, g_v);
    cudaGetSymbolAddress((void**)&o, g_o);

    cudaFuncSetAttribute(gemm_tc_kernel, cudaFuncAttributeMaxDynamicSharedMemorySize,
                         GSMEM);
    cudaFuncSetAttribute(attn_kernel, cudaFuncAttributeMaxDynamicSharedMemorySize,
                         ASMEM);

    rope_table_kernel<<<(L_ * 32 + 255) / 256, 256>>>();

    // fused QKV projection (+RoPE in epilogue)
    gemm_tc_kernel<<<dim3(D_ / 128, M_ / 128, 3), 256, GSMEM>>>(
        x, Wq, Wk, Wv, q, k, v, 1);

    attn_kernel<<<dim3(L_ / 128, B_ * H_), 256, ASMEM>>>(q, k, v, o);

    // output projection (no RoPE)
    gemm_tc_kernel<<<dim3(D_ / 128, M_ / 128, 1), 256, GSMEM>>>(
        o, Wo, Wo, Wo, out, out, out, 0);
}